// round 16
// baseline (speedup 1.0000x reference)
#include <cuda_runtime.h>
#include <cuda_bf16.h>
#include <math.h>
#include <stdint.h>

// ---------------- problem constants ----------------
#define BB 64
#define SS 64
#define TT 64
#define HH 1024
#define EE 1024
#define VV 32000
#define H3 3072

// ---------------- static device buffers (no allocation allowed) -------------
// Weight splits (hi/lo pairs, ids adjacent)
__device__ __nv_bfloat16 g_WihE_hi[2 * H3 * EE];
__device__ __nv_bfloat16 g_WihE_lo[2 * H3 * EE];
__device__ __nv_bfloat16 g_WhhE_hi[2 * H3 * HH];
__device__ __nv_bfloat16 g_WhhE_lo[2 * H3 * HH];
__device__ __nv_bfloat16 g_WihD_hi[2 * H3 * EE];
__device__ __nv_bfloat16 g_WihD_lo[2 * H3 * EE];
__device__ __nv_bfloat16 g_WhhD_hi[2 * H3 * HH];
__device__ __nv_bfloat16 g_WhhD_lo[2 * H3 * HH];
__device__ __nv_bfloat16 g_Wout_hi[(size_t)VV * HH];
__device__ __nv_bfloat16 g_Wout_lo[(size_t)VV * HH];
// Embedded inputs (time-major rows: row = step*B + b)
__device__ __nv_bfloat16 g_xenc_hi[SS * BB * EE];
__device__ __nv_bfloat16 g_xenc_lo[SS * BB * EE];
__device__ __nv_bfloat16 g_xdec_hi[(TT - 1) * BB * EE];
__device__ __nv_bfloat16 g_xdec_lo[(TT - 1) * BB * EE];
// Hidden state shadows
__device__ __nv_bfloat16 g_h0_hi[BB * HH];
__device__ __nv_bfloat16 g_h0_lo[BB * HH];
__device__ __nv_bfloat16 g_h1_hi[BB * HH];
__device__ __nv_bfloat16 g_h1_lo[BB * HH];
__device__ __nv_bfloat16 g_x1_hi[BB * HH];   // unmasked layer0 output (layer1 input)
__device__ __nv_bfloat16 g_x1_lo[BB * HH];
__device__ __nv_bfloat16 g_top_hi[(TT - 1) * BB * HH];  // decoder top states
__device__ __nv_bfloat16 g_top_lo[(TT - 1) * BB * HH];
// fp32 buffers
__device__ float g_gi0e[SS * BB * H3];        // precomputed layer0 gi (encoder)
__device__ float g_gi0d[(TT - 1) * BB * H3];  // precomputed layer0 gi (decoder)
__device__ float g_gh0[BB * H3];
__device__ float g_gi1[BB * H3];
__device__ float g_gh1[BB * H3];
__device__ float g_h0[BB * HH];
__device__ float g_h1[BB * HH];

// ---------------- buffer id resolution (device-side; host never needs symbol addrs)
__device__ __forceinline__ __nv_bfloat16* bfbuf(int id) {
    switch (id) {
        case 0:  return g_WihE_hi; case 1:  return g_WihE_lo;
        case 2:  return g_WhhE_hi; case 3:  return g_WhhE_lo;
        case 4:  return g_WihD_hi; case 5:  return g_WihD_lo;
        case 6:  return g_WhhD_hi; case 7:  return g_WhhD_lo;
        case 8:  return g_Wout_hi; case 9:  return g_Wout_lo;
        case 10: return g_xenc_hi; case 11: return g_xenc_lo;
        case 12: return g_xdec_hi; case 13: return g_xdec_lo;
        case 14: return g_h0_hi;   case 15: return g_h0_lo;
        case 16: return g_h1_hi;   case 17: return g_h1_lo;
        case 18: return g_x1_hi;   case 19: return g_x1_lo;
        case 20: return g_top_hi;  default: return g_top_lo;
    }
}
__device__ __forceinline__ float* f32buf(int id) {
    switch (id) {
        case 0: return g_gi0e;
        case 1: return g_gi0d;
        case 2: return g_gh0;
        case 3: return g_gi1;
        default: return g_gh1;
    }
}

// ---------------- fp32 -> bf16 hi/lo split ----------------
__device__ __forceinline__ void split_bf16(float v, __nv_bfloat16& hi, __nv_bfloat16& lo) {
    __nv_bfloat16 h = __float2bfloat16(v);
    hi = h;
    lo = __float2bfloat16(v - __bfloat162float(h));
}

// ---------------- weight split kernel ----------------
__global__ void split_kernel(const float* __restrict__ src, size_t n, int dst_hi_id) {
    size_t i = (size_t)blockIdx.x * blockDim.x + threadIdx.x;
    if (i >= n) return;
    __nv_bfloat16 h, l;
    split_bf16(src[i], h, l);
    bfbuf(dst_hi_id)[i] = h;
    bfbuf(dst_hi_id + 1)[i] = l;
}

// ---------------- embedding gather + split (time-major rows) ----------------
// row = s*64 + b ; token = toks[b*64 + s]  (both src_tokens [B,S=64] and trg [B,T=64])
__global__ void gather_kernel(const int* __restrict__ toks, const float* __restrict__ emb,
                              int dst_hi_id) {
    int row = blockIdx.x;
    int s = row >> 6, b = row & 63;
    int tok = toks[b * 64 + s];
    const float* src = emb + (size_t)tok * EE;
    __nv_bfloat16* hi = bfbuf(dst_hi_id) + (size_t)row * EE;
    __nv_bfloat16* lo = bfbuf(dst_hi_id + 1) + (size_t)row * EE;
    for (int e = threadIdx.x; e < EE; e += blockDim.x) {
        float v = (tok == 0) ? 0.0f : src[e];
        __nv_bfloat16 h, l;
        split_bf16(v, h, l);
        hi[e] = h;
        lo[e] = l;
    }
}

// ---------------- init kernels ----------------
__global__ void init_h_kernel() {
    int idx = blockIdx.x * blockDim.x + threadIdx.x;
    if (idx >= BB * HH) return;
    g_h0[idx] = 0.0f;
    g_h1[idx] = 0.0f;
    __nv_bfloat16 z = __float2bfloat16(0.0f);
    g_h0_hi[idx] = z; g_h0_lo[idx] = z;
    g_h1_hi[idx] = z; g_h1_lo[idx] = z;
}

__global__ void zero_out_kernel(float* __restrict__ out) {
    int idx = blockIdx.x * blockDim.x + threadIdx.x;
    if (idx >= BB * VV) return;
    int b = idx / VV, v = idx - b * VV;
    out[(size_t)b * TT * VV + v] = 0.0f;  // out[b][0][v] = 0
}

// ---------------- split-precision bf16 GEMM (C = sum_seg A_s @ B_s^T + bias) ---
// A_s: [M,K] bf16 row-major, B_s: [N,K] bf16 row-major. C fp32.
// mode 0: C[m*ldc + n]. mode 1: logits scatter out[(b*T + t)*V + n], b=m&63, t=(m>>6)+1.
struct GemmJob {
    int aid[3]; size_t aoff[3];
    int bid[3]; size_t boff[3];
    int nseg, K, M, N;
    const float* bias;
    int cid; size_t coff;
    float* cext;
    size_t ldc;
    int mode;
};
struct GemmLaunch { GemmJob j[2]; };

#define GBM 64
#define GBN 32
#define GBK 64
#define GPAD 8

__global__ void __launch_bounds__(128) gemm_kernel(GemmLaunch L) {
    const GemmJob jb = L.j[blockIdx.z];
    __shared__ __nv_bfloat16 As[GBM][GBK + GPAD];
    __shared__ __nv_bfloat16 Bs[GBN][GBK + GPAD];

    const int n0 = blockIdx.x * GBN;
    const int m0 = blockIdx.y * GBM;
    const int tid = threadIdx.x;
    const int warp = tid >> 5, lane = tid & 31;
    const int g = lane >> 2, tg = lane & 3;
    const int K = jb.K;

    float acc[4][4];
#pragma unroll
    for (int c = 0; c < 4; ++c)
#pragma unroll
        for (int r = 0; r < 4; ++r) acc[c][r] = 0.0f;

    for (int s = 0; s < jb.nseg; ++s) {
        const __nv_bfloat16* A = bfbuf(jb.aid[s]) + jb.aoff[s];
        const __nv_bfloat16* Bp = bfbuf(jb.bid[s]) + jb.boff[s];
        for (int k0 = 0; k0 < K; k0 += GBK) {
            __syncthreads();
            // load A tile 64x64: 512 8-elem chunks, 4 per thread
#pragma unroll
            for (int i = 0; i < 4; ++i) {
                int ch = tid + i * 128;
                int r = ch >> 3;
                int c = (ch & 7) * 8;
                uint4 v = *(const uint4*)(A + (size_t)(m0 + r) * K + k0 + c);
                *(uint4*)(&As[r][c]) = v;
            }
            // load B tile 32x64: 256 chunks, 2 per thread
#pragma unroll
            for (int i = 0; i < 2; ++i) {
                int ch = tid + i * 128;
                int r = ch >> 3;
                int c = (ch & 7) * 8;
                uint4 v = *(const uint4*)(Bp + (size_t)(n0 + r) * K + k0 + c);
                *(uint4*)(&Bs[r][c]) = v;
            }
            __syncthreads();
#pragma unroll
            for (int kk = 0; kk < GBK; kk += 16) {
                uint32_t a0 = *(const uint32_t*)&As[16 * warp + g][kk + 2 * tg];
                uint32_t a1 = *(const uint32_t*)&As[16 * warp + g + 8][kk + 2 * tg];
                uint32_t a2 = *(const uint32_t*)&As[16 * warp + g][kk + 2 * tg + 8];
                uint32_t a3 = *(const uint32_t*)&As[16 * warp + g + 8][kk + 2 * tg + 8];
#pragma unroll
                for (int c = 0; c < 4; ++c) {
                    uint32_t b0 = *(const uint32_t*)&Bs[8 * c + g][kk + 2 * tg];
                    uint32_t b1 = *(const uint32_t*)&Bs[8 * c + g][kk + 2 * tg + 8];
                    asm volatile(
                        "mma.sync.aligned.m16n8k16.row.col.f32.bf16.bf16.f32 "
                        "{%0,%1,%2,%3}, {%4,%5,%6,%7}, {%8,%9}, {%0,%1,%2,%3};\n"
                        : "+f"(acc[c][0]), "+f"(acc[c][1]), "+f"(acc[c][2]), "+f"(acc[c][3])
                        : "r"(a0), "r"(a1), "r"(a2), "r"(a3), "r"(b0), "r"(b1));
                }
            }
        }
    }

    float* C = jb.cext ? jb.cext : (f32buf(jb.cid) + jb.coff);
#pragma unroll
    for (int c = 0; c < 4; ++c) {
        int n = n0 + 8 * c + 2 * tg;
        float b0v = jb.bias ? jb.bias[n] : 0.0f;
        float b1v = jb.bias ? jb.bias[n + 1] : 0.0f;
        int mA = m0 + 16 * warp + g;
        int mB = mA + 8;
        if (jb.mode == 0) {
            C[(size_t)mA * jb.ldc + n]     = acc[c][0] + b0v;
            C[(size_t)mA * jb.ldc + n + 1] = acc[c][1] + b1v;
            C[(size_t)mB * jb.ldc + n]     = acc[c][2] + b0v;
            C[(size_t)mB * jb.ldc + n + 1] = acc[c][3] + b1v;
        } else {
            size_t oA = ((size_t)(mA & 63) * TT + (mA >> 6) + 1) * VV + n;
            size_t oB = ((size_t)(mB & 63) * TT + (mB >> 6) + 1) * VV + n;
            C[oA]     = acc[c][0] + b0v;
            C[oA + 1] = acc[c][1] + b1v;
            C[oB]     = acc[c][2] + b0v;
            C[oB + 1] = acc[c][3] + b1v;
        }
    }
}

// ---------------- GRU gate combine (exact fp32 math) ----------------
// r = sig(i_r+h_r); z = sig(i_z+h_z); n = tanh(i_n + r*h_n); hnew = (1-z)*n + z*h
__global__ void gates_kernel(int gi_id, size_t gi_off, int gh_id, int hsel,
                             int write_x1, int write_top, size_t top_off,
                             const int* __restrict__ lens, int t) {
    int idx = blockIdx.x * blockDim.x + threadIdx.x;
    if (idx >= BB * HH) return;
    int b = idx >> 10, j = idx & 1023;
    const float* gi = f32buf(gi_id) + gi_off + (size_t)b * H3;
    const float* gh = f32buf(gh_id) + (size_t)b * H3;
    float* h = hsel ? g_h1 : g_h0;
    __nv_bfloat16* hhi = hsel ? g_h1_hi : g_h0_hi;
    __nv_bfloat16* hlo = hsel ? g_h1_lo : g_h0_lo;

    float r = 1.0f / (1.0f + expf(-(gi[j] + gh[j])));
    float z = 1.0f / (1.0f + expf(-(gi[j + HH] + gh[j + HH])));
    float n = tanhf(gi[j + 2 * HH] + r * gh[j + 2 * HH]);
    float hold = h[idx];
    float hnew = (1.0f - z) * n + z * hold;

    if (write_x1) {
        __nv_bfloat16 xh, xl;
        split_bf16(hnew, xh, xl);
        g_x1_hi[idx] = xh;
        g_x1_lo[idx] = xl;
    }
    if (write_top) {
        __nv_bfloat16 th, tl;
        split_bf16(hnew, th, tl);
        g_top_hi[top_off + idx] = th;
        g_top_lo[top_off + idx] = tl;
    }
    float hs = hnew;
    if (lens && !(t < lens[b])) hs = hold;  // encoder packed-seq freeze
    h[idx] = hs;
    __nv_bfloat16 sh, sl;
    split_bf16(hs, sh, sl);
    hhi[idx] = sh;
    hlo[idx] = sl;
}

// ---------------- host-side helpers ----------------
static GemmJob make_job(int a_hi, size_t aoff, int b_hi, size_t boff, int K, int M, int N,
                        const float* bias, int cid, size_t coff, float* cext, size_t ldc,
                        int mode) {
    GemmJob J = {};
    // 3-pass split: hi*hi + hi*lo + lo*hi
    J.aid[0] = a_hi;     J.aoff[0] = aoff; J.bid[0] = b_hi;     J.boff[0] = boff;
    J.aid[1] = a_hi;     J.aoff[1] = aoff; J.bid[1] = b_hi + 1; J.boff[1] = boff;
    J.aid[2] = a_hi + 1; J.aoff[2] = aoff; J.bid[2] = b_hi;     J.boff[2] = boff;
    J.nseg = 3; J.K = K; J.M = M; J.N = N;
    J.bias = bias; J.cid = cid; J.coff = coff; J.cext = cext; J.ldc = ldc; J.mode = mode;
    return J;
}

static void launch_gemm1(const GemmJob& J) {
    GemmLaunch L = {};
    L.j[0] = J;
    dim3 grid(J.N / GBN, J.M / GBM, 1);
    gemm_kernel<<<grid, 128>>>(L);
}
static void launch_gemm2(const GemmJob& J0, const GemmJob& J1) {
    GemmLaunch L = {};
    L.j[0] = J0;
    L.j[1] = J1;
    dim3 grid(J0.N / GBN, J0.M / GBM, 2);
    gemm_kernel<<<grid, 128>>>(L);
}

extern "C" void kernel_launch(void* const* d_in, const int* in_sizes, int n_in,
                              void* d_out, int out_size) {
    (void)in_sizes; (void)n_in; (void)out_size;
    const int* src_tokens = (const int*)d_in[0];
    const int* src_len    = (const int*)d_in[1];
    const int* trg        = (const int*)d_in[2];
    const float* emb_enc  = (const float*)d_in[3];
    const float* Wih_enc  = (const float*)d_in[4];
    const float* Whh_enc  = (const float*)d_in[5];
    const float* bih_enc  = (const float*)d_in[6];
    const float* bhh_enc  = (const float*)d_in[7];
    const float* emb_dec  = (const float*)d_in[8];
    const float* Wih_dec  = (const float*)d_in[9];
    const float* Whh_dec  = (const float*)d_in[10];
    const float* bih_dec  = (const float*)d_in[11];
    const float* bhh_dec  = (const float*)d_in[12];
    const float* Wout     = (const float*)d_in[13];
    const float* bout     = (const float*)d_in[14];
    float* out = (float*)d_out;

    // ---- weight conversions (hi/lo bf16 split) ----
    {
        size_t nW = (size_t)2 * H3 * EE;
        int grd = (int)((nW + 255) / 256);
        split_kernel<<<grd, 256>>>(Wih_enc, nW, 0);
        split_kernel<<<grd, 256>>>(Whh_enc, nW, 2);
        split_kernel<<<grd, 256>>>(Wih_dec, nW, 4);
        split_kernel<<<grd, 256>>>(Whh_dec, nW, 6);
        size_t nO = (size_t)VV * HH;
        split_kernel<<<(int)((nO + 255) / 256), 256>>>(Wout, nO, 8);
    }

    // ---- embedding gathers (time-major) ----
    gather_kernel<<<SS * BB, 256>>>(src_tokens, emb_enc, 10);
    gather_kernel<<<(TT - 1) * BB, 256>>>(trg, emb_dec, 12);

    // ---- init ----
    init_h_kernel<<<(BB * HH + 255) / 256, 256>>>();
    zero_out_kernel<<<(BB * VV + 255) / 256, 256>>>(out);

    const size_t l1w = (size_t)H3 * EE;  // layer-1 weight offset (elements)

    // ---- precompute layer-0 input projections for all timesteps ----
    // gi0_enc[s*B+b, :] = x_enc @ Wih_enc[0]^T + bih_enc[0]
    launch_gemm1(make_job(10, 0, 0, 0, EE, SS * BB, H3, bih_enc, 0, 0, nullptr, H3, 0));
    // gi0_dec
    launch_gemm1(make_job(12, 0, 4, 0, EE, (TT - 1) * BB, H3, bih_dec, 1, 0, nullptr, H3, 0));

    // ---- encoder recurrence ----
    for (int t = 0; t < SS; ++t) {
        // gh0 = h0 @ Whh_enc[0]^T + bhh_enc[0]
        launch_gemm1(make_job(14, 0, 2, 0, HH, BB, H3, bhh_enc, 2, 0, nullptr, H3, 0));
        // layer0 gates: x1 = unmasked new h0; state h0 masked
        gates_kernel<<<256, 256>>>(0, (size_t)t * BB * H3, 2, 0, 1, 0, 0, src_len, t);
        // layer1: gi1 = x1 @ Wih_enc[1]^T + bih1 ; gh1 = h1 @ Whh_enc[1]^T + bhh1
        launch_gemm2(
            make_job(18, 0, 0, l1w, HH, BB, H3, bih_enc + H3, 3, 0, nullptr, H3, 0),
            make_job(16, 0, 2, l1w, HH, BB, H3, bhh_enc + H3, 4, 0, nullptr, H3, 0));
        gates_kernel<<<256, 256>>>(3, 0, 4, 1, 0, 0, 0, src_len, t);
    }

    // ---- decoder recurrence (teacher forcing) ----
    for (int s = 0; s < TT - 1; ++s) {
        launch_gemm1(make_job(14, 0, 6, 0, HH, BB, H3, bhh_dec, 2, 0, nullptr, H3, 0));
        gates_kernel<<<256, 256>>>(1, (size_t)s * BB * H3, 2, 0, 1, 0, 0, nullptr, 0);
        launch_gemm2(
            make_job(18, 0, 4, l1w, HH, BB, H3, bih_dec + H3, 3, 0, nullptr, H3, 0),
            make_job(16, 0, 6, l1w, HH, BB, H3, bhh_dec + H3, 4, 0, nullptr, H3, 0));
        // layer1 gates: store top state into g_top at row s*B + b
        gates_kernel<<<256, 256>>>(3, 0, 4, 1, 0, 1, (size_t)s * BB * HH, nullptr, 0);
    }

    // ---- batched vocab projection: logits = top @ Wout^T + bout, scattered to out ----
    launch_gemm1(make_job(20, 0, 8, 0, HH, (TT - 1) * BB, VV, bout, 0, 0, out, 0, 1));
}

// round 17
// speedup vs baseline: 1.0044x; 1.0044x over previous
#include <cuda_runtime.h>
#include <cuda_bf16.h>
#include <math.h>
#include <stdint.h>

// ---------------- problem constants ----------------
#define BB 64
#define SS 64
#define TT 64
#define HH 1024
#define EE 1024
#define VV 32000
#define H3 3072

// ---------------- static device buffers (no allocation allowed) -------------
// Weight splits (hi/lo pairs, ids adjacent)
__device__ __nv_bfloat16 g_WihE_hi[2 * H3 * EE];
__device__ __nv_bfloat16 g_WihE_lo[2 * H3 * EE];
__device__ __nv_bfloat16 g_WhhE_hi[2 * H3 * HH];
__device__ __nv_bfloat16 g_WhhE_lo[2 * H3 * HH];
__device__ __nv_bfloat16 g_WihD_hi[2 * H3 * EE];
__device__ __nv_bfloat16 g_WihD_lo[2 * H3 * EE];
__device__ __nv_bfloat16 g_WhhD_hi[2 * H3 * HH];
__device__ __nv_bfloat16 g_WhhD_lo[2 * H3 * HH];
__device__ __nv_bfloat16 g_Wout_hi[(size_t)VV * HH];
__device__ __nv_bfloat16 g_Wout_lo[(size_t)VV * HH];
// Embedded inputs (time-major rows: row = step*B + b)
__device__ __nv_bfloat16 g_xenc_hi[SS * BB * EE];
__device__ __nv_bfloat16 g_xenc_lo[SS * BB * EE];
__device__ __nv_bfloat16 g_xdec_hi[(TT - 1) * BB * EE];
__device__ __nv_bfloat16 g_xdec_lo[(TT - 1) * BB * EE];
// Hidden state shadows
__device__ __nv_bfloat16 g_h0_hi[BB * HH];
__device__ __nv_bfloat16 g_h0_lo[BB * HH];
__device__ __nv_bfloat16 g_h1_hi[BB * HH];
__device__ __nv_bfloat16 g_h1_lo[BB * HH];
__device__ __nv_bfloat16 g_x1_hi[BB * HH];   // unmasked layer0 output (layer1 input)
__device__ __nv_bfloat16 g_x1_lo[BB * HH];
__device__ __nv_bfloat16 g_top_hi[(TT - 1) * BB * HH];  // decoder top states
__device__ __nv_bfloat16 g_top_lo[(TT - 1) * BB * HH];
// fp32 buffers
__device__ float g_gi0e[SS * BB * H3];        // precomputed layer0 gi (encoder)
__device__ float g_gi0d[(TT - 1) * BB * H3];  // precomputed layer0 gi (decoder)
__device__ float g_gh0[BB * H3];
__device__ float g_gi1[BB * H3];
__device__ float g_gh1[BB * H3];
__device__ float g_h0[BB * HH];
__device__ float g_h1[BB * HH];

// ---------------- buffer id resolution (device-side; host never needs symbol addrs)
__device__ __forceinline__ __nv_bfloat16* bfbuf(int id) {
    switch (id) {
        case 0:  return g_WihE_hi; case 1:  return g_WihE_lo;
        case 2:  return g_WhhE_hi; case 3:  return g_WhhE_lo;
        case 4:  return g_WihD_hi; case 5:  return g_WihD_lo;
        case 6:  return g_WhhD_hi; case 7:  return g_WhhD_lo;
        case 8:  return g_Wout_hi; case 9:  return g_Wout_lo;
        case 10: return g_xenc_hi; case 11: return g_xenc_lo;
        case 12: return g_xdec_hi; case 13: return g_xdec_lo;
        case 14: return g_h0_hi;   case 15: return g_h0_lo;
        case 16: return g_h1_hi;   case 17: return g_h1_lo;
        case 18: return g_x1_hi;   case 19: return g_x1_lo;
        case 20: return g_top_hi;  default: return g_top_lo;
    }
}
__device__ __forceinline__ float* f32buf(int id) {
    switch (id) {
        case 0: return g_gi0e;
        case 1: return g_gi0d;
        case 2: return g_gh0;
        case 3: return g_gi1;
        default: return g_gh1;
    }
}

// ---------------- fp32 -> bf16 hi/lo split ----------------
__device__ __forceinline__ void split_bf16(float v, __nv_bfloat16& hi, __nv_bfloat16& lo) {
    __nv_bfloat16 h = __float2bfloat16(v);
    hi = h;
    lo = __float2bfloat16(v - __bfloat162float(h));
}

// ---------------- weight split kernel ----------------
__global__ void split_kernel(const float* __restrict__ src, size_t n, int dst_hi_id) {
    size_t i = (size_t)blockIdx.x * blockDim.x + threadIdx.x;
    if (i >= n) return;
    __nv_bfloat16 h, l;
    split_bf16(src[i], h, l);
    bfbuf(dst_hi_id)[i] = h;
    bfbuf(dst_hi_id + 1)[i] = l;
}

// ---------------- embedding gather + split (time-major rows) ----------------
// row = s*64 + b ; token = toks[b*64 + s]  (both src_tokens [B,S=64] and trg [B,T=64])
__global__ void gather_kernel(const int* __restrict__ toks, const float* __restrict__ emb,
                              int dst_hi_id) {
    int row = blockIdx.x;
    int s = row >> 6, b = row & 63;
    int tok = toks[b * 64 + s];
    const float* src = emb + (size_t)tok * EE;
    __nv_bfloat16* hi = bfbuf(dst_hi_id) + (size_t)row * EE;
    __nv_bfloat16* lo = bfbuf(dst_hi_id + 1) + (size_t)row * EE;
    for (int e = threadIdx.x; e < EE; e += blockDim.x) {
        float v = (tok == 0) ? 0.0f : src[e];
        __nv_bfloat16 h, l;
        split_bf16(v, h, l);
        hi[e] = h;
        lo[e] = l;
    }
}

// ---------------- init kernels ----------------
__global__ void init_h_kernel() {
    int idx = blockIdx.x * blockDim.x + threadIdx.x;
    if (idx >= BB * HH) return;
    g_h0[idx] = 0.0f;
    g_h1[idx] = 0.0f;
    __nv_bfloat16 z = __float2bfloat16(0.0f);
    g_h0_hi[idx] = z; g_h0_lo[idx] = z;
    g_h1_hi[idx] = z; g_h1_lo[idx] = z;
}

__global__ void zero_out_kernel(float* __restrict__ out) {
    int idx = blockIdx.x * blockDim.x + threadIdx.x;
    if (idx >= BB * VV) return;
    int b = idx / VV, v = idx - b * VV;
    out[(size_t)b * TT * VV + v] = 0.0f;  // out[b][0][v] = 0
}

// ---------------- split-precision bf16 GEMM (C = sum_seg A_s @ B_s^T + bias) ---
// A_s: [M,K] bf16 row-major, B_s: [N,K] bf16 row-major. C fp32.
// mode 0: C[m*ldc + n]. mode 1: logits scatter out[(b*T + t)*V + n], b=m&63, t=(m>>6)+1.
struct GemmJob {
    int aid[3]; size_t aoff[3];
    int bid[3]; size_t boff[3];
    int nseg, K, M, N;
    const float* bias;
    int cid; size_t coff;
    float* cext;
    size_t ldc;
    int mode;
};
struct GemmLaunch { GemmJob j[2]; };

#define GBM 64
#define GBN 32
#define GBK 64
#define GPAD 8

__global__ void __launch_bounds__(128) gemm_kernel(GemmLaunch L) {
    const GemmJob jb = L.j[blockIdx.z];
    __shared__ __nv_bfloat16 As[GBM][GBK + GPAD];
    __shared__ __nv_bfloat16 Bs[GBN][GBK + GPAD];

    const int n0 = blockIdx.x * GBN;
    const int m0 = blockIdx.y * GBM;
    const int tid = threadIdx.x;
    const int warp = tid >> 5, lane = tid & 31;
    const int g = lane >> 2, tg = lane & 3;
    const int K = jb.K;

    float acc[4][4];
#pragma unroll
    for (int c = 0; c < 4; ++c)
#pragma unroll
        for (int r = 0; r < 4; ++r) acc[c][r] = 0.0f;

    for (int s = 0; s < jb.nseg; ++s) {
        const __nv_bfloat16* A = bfbuf(jb.aid[s]) + jb.aoff[s];
        const __nv_bfloat16* Bp = bfbuf(jb.bid[s]) + jb.boff[s];
        for (int k0 = 0; k0 < K; k0 += GBK) {
            __syncthreads();
            // load A tile 64x64: 512 8-elem chunks, 4 per thread
#pragma unroll
            for (int i = 0; i < 4; ++i) {
                int ch = tid + i * 128;
                int r = ch >> 3;
                int c = (ch & 7) * 8;
                uint4 v = *(const uint4*)(A + (size_t)(m0 + r) * K + k0 + c);
                *(uint4*)(&As[r][c]) = v;
            }
            // load B tile 32x64: 256 chunks, 2 per thread
#pragma unroll
            for (int i = 0; i < 2; ++i) {
                int ch = tid + i * 128;
                int r = ch >> 3;
                int c = (ch & 7) * 8;
                uint4 v = *(const uint4*)(Bp + (size_t)(n0 + r) * K + k0 + c);
                *(uint4*)(&Bs[r][c]) = v;
            }
            __syncthreads();
#pragma unroll
            for (int kk = 0; kk < GBK; kk += 16) {
                uint32_t a0 = *(const uint32_t*)&As[16 * warp + g][kk + 2 * tg];
                uint32_t a1 = *(const uint32_t*)&As[16 * warp + g + 8][kk + 2 * tg];
                uint32_t a2 = *(const uint32_t*)&As[16 * warp + g][kk + 2 * tg + 8];
                uint32_t a3 = *(const uint32_t*)&As[16 * warp + g + 8][kk + 2 * tg + 8];
#pragma unroll
                for (int c = 0; c < 4; ++c) {
                    uint32_t b0 = *(const uint32_t*)&Bs[8 * c + g][kk + 2 * tg];
                    uint32_t b1 = *(const uint32_t*)&Bs[8 * c + g][kk + 2 * tg + 8];
                    asm volatile(
                        "mma.sync.aligned.m16n8k16.row.col.f32.bf16.bf16.f32 "
                        "{%0,%1,%2,%3}, {%4,%5,%6,%7}, {%8,%9}, {%0,%1,%2,%3};\n"
                        : "+f"(acc[c][0]), "+f"(acc[c][1]), "+f"(acc[c][2]), "+f"(acc[c][3])
                        : "r"(a0), "r"(a1), "r"(a2), "r"(a3), "r"(b0), "r"(b1));
                }
            }
        }
    }

    float* C = jb.cext ? jb.cext : (f32buf(jb.cid) + jb.coff);
#pragma unroll
    for (int c = 0; c < 4; ++c) {
        int n = n0 + 8 * c + 2 * tg;
        float b0v = jb.bias ? jb.bias[n] : 0.0f;
        float b1v = jb.bias ? jb.bias[n + 1] : 0.0f;
        int mA = m0 + 16 * warp + g;
        int mB = mA + 8;
        if (jb.mode == 0) {
            C[(size_t)mA * jb.ldc + n]     = acc[c][0] + b0v;
            C[(size_t)mA * jb.ldc + n + 1] = acc[c][1] + b1v;
            C[(size_t)mB * jb.ldc + n]     = acc[c][2] + b0v;
            C[(size_t)mB * jb.ldc + n + 1] = acc[c][3] + b1v;
        } else {
            size_t oA = ((size_t)(mA & 63) * TT + (mA >> 6) + 1) * VV + n;
            size_t oB = ((size_t)(mB & 63) * TT + (mB >> 6) + 1) * VV + n;
            C[oA]     = acc[c][0] + b0v;
            C[oA + 1] = acc[c][1] + b1v;
            C[oB]     = acc[c][2] + b0v;
            C[oB + 1] = acc[c][3] + b1v;
        }
    }
}

// ---------------- GRU gate combine (exact fp32 math) ----------------
// r = sig(i_r+h_r); z = sig(i_z+h_z); n = tanh(i_n + r*h_n); hnew = (1-z)*n + z*h
__global__ void gates_kernel(int gi_id, size_t gi_off, int gh_id, int hsel,
                             int write_x1, int write_top, size_t top_off,
                             const int* __restrict__ lens, int t) {
    int idx = blockIdx.x * blockDim.x + threadIdx.x;
    if (idx >= BB * HH) return;
    int b = idx >> 10, j = idx & 1023;
    const float* gi = f32buf(gi_id) + gi_off + (size_t)b * H3;
    const float* gh = f32buf(gh_id) + (size_t)b * H3;
    float* h = hsel ? g_h1 : g_h0;
    __nv_bfloat16* hhi = hsel ? g_h1_hi : g_h0_hi;
    __nv_bfloat16* hlo = hsel ? g_h1_lo : g_h0_lo;

    float r = 1.0f / (1.0f + expf(-(gi[j] + gh[j])));
    float z = 1.0f / (1.0f + expf(-(gi[j + HH] + gh[j + HH])));
    float n = tanhf(gi[j + 2 * HH] + r * gh[j + 2 * HH]);
    float hold = h[idx];
    float hnew = (1.0f - z) * n + z * hold;

    if (write_x1) {
        __nv_bfloat16 xh, xl;
        split_bf16(hnew, xh, xl);
        g_x1_hi[idx] = xh;
        g_x1_lo[idx] = xl;
    }
    if (write_top) {
        __nv_bfloat16 th, tl;
        split_bf16(hnew, th, tl);
        g_top_hi[top_off + idx] = th;
        g_top_lo[top_off + idx] = tl;
    }
    float hs = hnew;
    if (lens && !(t < lens[b])) hs = hold;  // encoder packed-seq freeze
    h[idx] = hs;
    __nv_bfloat16 sh, sl;
    split_bf16(hs, sh, sl);
    hhi[idx] = sh;
    hlo[idx] = sl;
}

// ---------------- host-side helpers ----------------
static GemmJob make_job(int a_hi, size_t aoff, int b_hi, size_t boff, int K, int M, int N,
                        const float* bias, int cid, size_t coff, float* cext, size_t ldc,
                        int mode) {
    GemmJob J = {};
    // 3-pass split: hi*hi + hi*lo + lo*hi
    J.aid[0] = a_hi;     J.aoff[0] = aoff; J.bid[0] = b_hi;     J.boff[0] = boff;
    J.aid[1] = a_hi;     J.aoff[1] = aoff; J.bid[1] = b_hi + 1; J.boff[1] = boff;
    J.aid[2] = a_hi + 1; J.aoff[2] = aoff; J.bid[2] = b_hi;     J.boff[2] = boff;
    J.nseg = 3; J.K = K; J.M = M; J.N = N;
    J.bias = bias; J.cid = cid; J.coff = coff; J.cext = cext; J.ldc = ldc; J.mode = mode;
    return J;
}

static void launch_gemm1(const GemmJob& J) {
    GemmLaunch L = {};
    L.j[0] = J;
    dim3 grid(J.N / GBN, J.M / GBM, 1);
    gemm_kernel<<<grid, 128>>>(L);
}
static void launch_gemm2(const GemmJob& J0, const GemmJob& J1) {
    GemmLaunch L = {};
    L.j[0] = J0;
    L.j[1] = J1;
    dim3 grid(J0.N / GBN, J0.M / GBM, 2);
    gemm_kernel<<<grid, 128>>>(L);
}

extern "C" void kernel_launch(void* const* d_in, const int* in_sizes, int n_in,
                              void* d_out, int out_size) {
    (void)in_sizes; (void)n_in; (void)out_size;
    const int* src_tokens = (const int*)d_in[0];
    const int* src_len    = (const int*)d_in[1];
    const int* trg        = (const int*)d_in[2];
    const float* emb_enc  = (const float*)d_in[3];
    const float* Wih_enc  = (const float*)d_in[4];
    const float* Whh_enc  = (const float*)d_in[5];
    const float* bih_enc  = (const float*)d_in[6];
    const float* bhh_enc  = (const float*)d_in[7];
    const float* emb_dec  = (const float*)d_in[8];
    const float* Wih_dec  = (const float*)d_in[9];
    const float* Whh_dec  = (const float*)d_in[10];
    const float* bih_dec  = (const float*)d_in[11];
    const float* bhh_dec  = (const float*)d_in[12];
    const float* Wout     = (const float*)d_in[13];
    const float* bout     = (const float*)d_in[14];
    float* out = (float*)d_out;

    // ---- weight conversions (hi/lo bf16 split) ----
    {
        size_t nW = (size_t)2 * H3 * EE;
        int grd = (int)((nW + 255) / 256);
        split_kernel<<<grd, 256>>>(Wih_enc, nW, 0);
        split_kernel<<<grd, 256>>>(Whh_enc, nW, 2);
        split_kernel<<<grd, 256>>>(Wih_dec, nW, 4);
        split_kernel<<<grd, 256>>>(Whh_dec, nW, 6);
        size_t nO = (size_t)VV * HH;
        split_kernel<<<(int)((nO + 255) / 256), 256>>>(Wout, nO, 8);
    }

    // ---- embedding gathers (time-major) ----
    gather_kernel<<<SS * BB, 256>>>(src_tokens, emb_enc, 10);
    gather_kernel<<<(TT - 1) * BB, 256>>>(trg, emb_dec, 12);

    // ---- init ----
    init_h_kernel<<<(BB * HH + 255) / 256, 256>>>();
    zero_out_kernel<<<(BB * VV + 255) / 256, 256>>>(out);

    const size_t l1w = (size_t)H3 * EE;  // layer-1 weight offset (elements)

    // ---- precompute layer-0 input projections for all timesteps ----
    // gi0_enc[s*B+b, :] = x_enc @ Wih_enc[0]^T + bih_enc[0]
    launch_gemm1(make_job(10, 0, 0, 0, EE, SS * BB, H3, bih_enc, 0, 0, nullptr, H3, 0));
    // gi0_dec
    launch_gemm1(make_job(12, 0, 4, 0, EE, (TT - 1) * BB, H3, bih_dec, 1, 0, nullptr, H3, 0));

    // ---- encoder recurrence ----
    for (int t = 0; t < SS; ++t) {
        // gh0 = h0 @ Whh_enc[0]^T + bhh_enc[0]
        launch_gemm1(make_job(14, 0, 2, 0, HH, BB, H3, bhh_enc, 2, 0, nullptr, H3, 0));
        // layer0 gates: x1 = unmasked new h0; state h0 masked
        gates_kernel<<<256, 256>>>(0, (size_t)t * BB * H3, 2, 0, 1, 0, 0, src_len, t);
        // layer1: gi1 = x1 @ Wih_enc[1]^T + bih1 ; gh1 = h1 @ Whh_enc[1]^T + bhh1
        launch_gemm2(
            make_job(18, 0, 0, l1w, HH, BB, H3, bih_enc + H3, 3, 0, nullptr, H3, 0),
            make_job(16, 0, 2, l1w, HH, BB, H3, bhh_enc + H3, 4, 0, nullptr, H3, 0));
        gates_kernel<<<256, 256>>>(3, 0, 4, 1, 0, 0, 0, src_len, t);
    }

    // ---- decoder recurrence (teacher forcing) ----
    for (int s = 0; s < TT - 1; ++s) {
        launch_gemm1(make_job(14, 0, 6, 0, HH, BB, H3, bhh_dec, 2, 0, nullptr, H3, 0));
        gates_kernel<<<256, 256>>>(1, (size_t)s * BB * H3, 2, 0, 1, 0, 0, nullptr, 0);
        launch_gemm2(
            make_job(18, 0, 4, l1w, HH, BB, H3, bih_dec + H3, 3, 0, nullptr, H3, 0),
            make_job(16, 0, 6, l1w, HH, BB, H3, bhh_dec + H3, 4, 0, nullptr, H3, 0));
        // layer1 gates: store top state into g_top at row s*B + b
        gates_kernel<<<256, 256>>>(3, 0, 4, 1, 0, 1, (size_t)s * BB * HH, nullptr, 0);
    }

    // ---- batched vocab projection: logits = top @ Wout^T + bout, scattered to out ----
    launch_gemm1(make_job(20, 0, 8, 0, HH, (TT - 1) * BB, VV, bout, 0, 0, out, 0, 1));
}